// round 8
// baseline (speedup 1.0000x reference)
#include <cuda_runtime.h>
#include <cstdint>

typedef unsigned long long ull;

#define Bb 2048
#define Tt 1000
#define Ii 40
#define Hh 16
#define TS 20
#define NCH (Tt/TS)            /* 50 chunks of 20 steps */
#define PADF 8
#define BSTR (TS*Ii + PADF)    /* 808 floats per chunk slot */

// -------- device-global scratch (no allocation allowed) --------
__device__ float2 g_wp[32*20];       // per neuron-branch nb: 20 dense weight pairs, pre-scaled by (1-a)(1-b)
__device__ float  g_alpha2[32];      // alpha[h] replicated per branch lane
__device__ float  g_betab[32];       // beta per neuron-branch
__device__ float2 g_w2[Hh];          // (W2[0][h], W2[1][h])
__device__ float2 g_b2c;
__device__ uint32_t g_tmask[Bb*Tt];  // per (b,t) 32-bit spike mask (bit nb, pair-duplicated) — 8MB

// -------- packed f32x2 helpers --------
__device__ __forceinline__ ull pk2(float a, float b){ ull r; asm("mov.b64 %0,{%1,%2};":"=l"(r):"f"(a),"f"(b)); return r; }
__device__ __forceinline__ void upk2(ull v, float&a, float&b){ asm("mov.b64 {%0,%1},%2;":"=f"(a),"=f"(b):"l"(v)); }
__device__ __forceinline__ ull fma2(ull a, ull b, ull c){ ull d; asm("fma.rn.f32x2 %0,%1,%2,%3;":"=l"(d):"l"(a),"l"(b),"l"(c)); return d; }
__device__ __forceinline__ ull mul2(ull a, ull b){ ull d; asm("mul.rn.f32x2 %0,%1,%2;":"=l"(d):"l"(a),"l"(b)); return d; }
__device__ __forceinline__ ull add2(ull a, ull b){ ull d; asm("add.rn.f32x2 %0,%1,%2;":"=l"(d):"l"(a),"l"(b)); return d; }
// non-volatile: let ptxas software-pipeline loads across timesteps
__device__ __forceinline__ void lds128(uint32_t a, ull&u, ull&v){ asm("ld.shared.v2.b64 {%0,%1},[%2];":"=l"(u),"=l"(v):"r"(a)); }
__device__ __forceinline__ void cpa16(uint32_t d, const void* s){ asm volatile("cp.async.cg.shared.global [%0],[%1],16;"::"r"(d),"l"(s)); }
__device__ __forceinline__ void cp_commit(){ asm volatile("cp.async.commit_group;"); }

// ---------------- init: scalar outputs ----------------
__global__ void init_kernel(float* __restrict__ out, long long corrIdx, long long totIdx){
  if (threadIdx.x == 0){
    out[0] = 0.0f;
    out[corrIdx] = 0.0f;
    int cnt = 0;
    for (int t=0;t<Tt;t++) cnt += ((t>10) && (((t-10)%15)>5)) ? 1 : 0;
    out[totIdx] = (float)cnt * (float)Bb;   // flags.sum() * B
  }
}

// ---------------- pack: pre-scale weights (parallel) ----------------
__global__ void pack_kernel(const float* __restrict__ W1, const float* __restrict__ tau_m,
                            const float* __restrict__ tau_n, const float* __restrict__ mask,
                            const float* __restrict__ W2, const float* __restrict__ b2){
  int tid = threadIdx.x;                    // 640 threads: (nb, k) pairs
  if (tid < 32*20){
    int nb = tid / 20, k = tid % 20;
    int h = nb >> 1;
    float a  = 1.0f/(1.0f + expf(-tau_m[h]));
    float be = 1.0f/(1.0f + expf(-tau_n[nb]));
    float s  = (1.0f - a)*(1.0f - be);      // fold (1-alpha)(1-beta) into weights
    int r = nb*Ii;
    g_wp[tid] = make_float2(W1[r+2*k]*mask[r+2*k]*s, W1[r+2*k+1]*mask[r+2*k+1]*s);
    if (k == 0){
      g_alpha2[nb] = a;
      g_betab[nb]  = be;
      if ((nb & 1) == 0) g_w2[h] = make_float2(W2[h], W2[Hh+h]);
    }
  }
  if (tid == 0) g_b2c = make_float2(b2[0], b2[1]);
}

// ---------------- main: warp = 1 batch, lane = neuron-branch ----------------
// Each lane keeps BOTH branch states (d0 = own, d1 = other via off-chain shfl of cdot),
// so the serial chain per step is just fma+fadd+fma+cmp. 2-step interleaved dots.
// Chunk epilogue: 20-ballot transpose -> per-timestep masks stored coalesced.
__global__ void __launch_bounds__(32) snn_kernel(const float* __restrict__ x){
  __shared__ __align__(16) float sx[2*BSTR];
  const int lane = threadIdx.x;            // nb = 2h + br
  const int b    = blockIdx.x;

  ull w[20];
  #pragma unroll
  for (int k=0;k<20;k++){ float2 ww = g_wp[lane*20+k]; w[k]=pk2(ww.x,ww.y); }
  const float alpha = g_alpha2[lane];
  const float bown  = g_betab[lane];
  const float both  = g_betab[lane^1];

  float d0=0.f, d1=0.f, mem=0.f, asel=0.f;
  uint32_t sbase = (uint32_t)__cvta_generic_to_shared(sx);
  uint32_t* mrow = g_tmask + (size_t)b * Tt;
  const float4* xg = (const float4*)x + (size_t)b * Tt * 10;   // 40 f32 = 10 float4/step

  // stage chunk 0 (200 float4)
  for (int j=lane;j<200;j+=32) cpa16(sbase + (uint32_t)j*16u, xg + j);
  cp_commit();

  int buf = 0;
  for (int c=0;c<NCH;c++){
    if (c+1 < NCH){
      uint32_t sb = sbase + (uint32_t)((buf^1)*BSTR)*4u;
      const float4* p = xg + (size_t)(c+1)*200;
      for (int j=lane;j<200;j+=32) cpa16(sb + (uint32_t)j*16u, p + j);
      cp_commit();
      asm volatile("cp.async.wait_group 1;" ::: "memory");
    } else {
      asm volatile("cp.async.wait_group 0;" ::: "memory");
    }
    __syncwarp();                            // cross-lane visibility of staged x

    uint32_t xaddr = sbase + (uint32_t)(buf*BSTR)*4u;
    uint32_t bits = 0;

    #pragma unroll 2
    for (int pp=0; pp<TS/2; pp++){
      // two timesteps' dots interleaved: 4 independent FFMA2 chains
      ull xa0,xa1, xb0,xb1;
      lds128(xaddr,        xa0, xa1);        // t = 2pp
      lds128(xaddr + 160u, xb0, xb1);        // t = 2pp+1
      ull A0 = mul2(w[0], xa0), A1 = mul2(w[1], xa1);
      ull B0 = mul2(w[0], xb0), B1 = mul2(w[1], xb1);
      #pragma unroll
      for (int j=1;j<10;j++){
        ull u0,u1, v0,v1;
        lds128(xaddr + 16u*j,        u0, u1);
        lds128(xaddr + 160u + 16u*j, v0, v1);
        A0 = fma2(w[2*j],   u0, A0);
        A1 = fma2(w[2*j+1], u1, A1);
        B0 = fma2(w[2*j],   v0, B0);
        B1 = fma2(w[2*j+1], v1, B1);
      }
      float f0,f1;
      ull sA = add2(A0,A1); upk2(sA,f0,f1); float cA = f0+f1;
      ull sB = add2(B0,B1); upk2(sB,f0,f1); float cB = f0+f1;
      // branch-exchange OFF the serial chain
      float cOA = __shfl_xor_sync(0xffffffffu, cA, 1);
      float cOB = __shfl_xor_sync(0xffffffffu, cB, 1);

      // step A (both branch states kept locally; pair-identical)
      d0 = fmaf(bown, d0, cA);
      d1 = fmaf(both, d1, cOA);
      mem = fmaf(alpha, mem, d0 + d1) - asel;
      bool spA = mem > 1.0f;
      asel = spA ? alpha : 0.0f;
      bits |= (spA ? 1u : 0u) << (2*pp);

      // step B
      d0 = fmaf(bown, d0, cB);
      d1 = fmaf(both, d1, cOB);
      mem = fmaf(alpha, mem, d0 + d1) - asel;
      bool spB = mem > 1.0f;
      asel = spB ? alpha : 0.0f;
      bits |= (spB ? 1u : 0u) << (2*pp+1);

      xaddr += 320u;                         // 2 steps = 80 floats
    }

    // chunk epilogue: transpose 20 per-lane bit-streams into per-timestep masks
    uint32_t m = 0;
    #pragma unroll
    for (int s=0;s<TS;s++){
      uint32_t v = __ballot_sync(0xffffffffu, (bits>>s)&1u);
      if (lane == s) m = v;
    }
    if (lane < TS) mrow[c*TS + lane] = m;    // coalesced STG.32 x20
    buf ^= 1;
  }
}

// ---------------- logits + loss + accuracy: thread = one (b,t) point ----------------
__global__ void loss_kernel(const int* __restrict__ target, float* __restrict__ out,
                            long long corrIdx){
  __shared__ float2 lut[4][256];
  for (int m = threadIdx.x; m < 256; m += blockDim.x){
    #pragma unroll
    for (int q=0;q<4;q++){
      float2 a = make_float2(0.f,0.f);
      #pragma unroll
      for (int j=0;j<4;j++){
        if ((m>>(2*j))&1){ float2 v = g_w2[4*q+j]; a.x += v.x; a.y += v.y; }
      }
      lut[q][m] = a;
    }
  }
  __syncthreads();

  int idx = blockIdx.x * blockDim.x + threadIdx.x;
  float lossv = 0.f, corr = 0.f;
  if (idx < Bb*Tt){
    int t = idx % Tt;
    uint32_t m32 = g_tmask[idx];
    float2 c0 = lut[0][m32 & 0xFF];
    float2 c1 = lut[1][(m32>>8) & 0xFF];
    float2 c2 = lut[2][(m32>>16) & 0xFF];
    float2 c3 = lut[3][(m32>>24) & 0xFF];
    float2 b2v = g_b2c;
    float z0 = ((c0.x+c1.x)+(c2.x+c3.x)) + b2v.x;
    float z1 = ((c0.y+c1.y)+(c2.y+c3.y)) + b2v.y;
    out[1 + 2*(size_t)idx]     = z0;
    out[1 + 2*(size_t)idx + 1] = z1;
    if ((t>10) && (((t-10)%15)>5)){
      int tgt = target[idx];
      // closed-form double-softmax CE for 2 classes:
      // q = p1-p0 = (e^s-1)/(e^s+1), s = z1-z0
      // loss = ln2 ± q/2 + q^2/8 - q^4/192 + q^6/2880   (|q|<=1, err<3e-5)
      float s  = z1 - z0;
      float e  = __expf(s);
      float r  = __fdividef(1.0f, 1.0f + e);
      float q  = (e - 1.0f) * r;
      float q2 = q*q;
      float even = 0.6931471805599453f
                 + q2*(0.125f + q2*(-5.208333333e-3f + q2*3.472222222e-4f));
      float lossp = even + ((tgt==0) ? 0.5f : -0.5f) * q;
      lossv = lossp * (1.0f/(float)Bb);
      corr  = ((((s>0.0f)?1:0)==tgt)) ? 1.0f : 0.0f;
    }
  }
  #pragma unroll
  for (int off=16; off; off>>=1){
    lossv += __shfl_xor_sync(0xffffffffu, lossv, off);
    corr  += __shfl_xor_sync(0xffffffffu, corr,  off);
  }
  __shared__ float sl[32], sc[32];
  int wq = threadIdx.x>>5, ln = threadIdx.x&31;
  if (ln==0){ sl[wq]=lossv; sc[wq]=corr; }
  __syncthreads();
  if (wq==0){
    int nw = blockDim.x>>5;
    lossv = (ln<nw)? sl[ln]:0.f;
    corr  = (ln<nw)? sc[ln]:0.f;
    #pragma unroll
    for (int off=4; off; off>>=1){
      lossv += __shfl_xor_sync(0xffffffffu,lossv,off);
      corr  += __shfl_xor_sync(0xffffffffu,corr, off);
    }
    if (ln==0){ atomicAdd(out, lossv); atomicAdd(out+corrIdx, corr); }
  }
}

extern "C" void kernel_launch(void* const* d_in, const int* in_sizes, int n_in,
                              void* d_out, int out_size){
  const float* x      = (const float*)d_in[0];
  const int*   target = (const int*)  d_in[1];
  const float* W1     = (const float*)d_in[2];
  const float* tau_m  = (const float*)d_in[3];
  const float* tau_n  = (const float*)d_in[4];
  const float* mask   = (const float*)d_in[5];
  const float* W2     = (const float*)d_in[6];
  const float* b2     = (const float*)d_in[7];
  float* out = (float*)d_out;
  long long corrIdx = (long long)out_size - 2;   // layout: [loss, logits(B*T*2), correct, total]
  long long totIdx  = (long long)out_size - 1;

  init_kernel<<<1, 32>>>(out, corrIdx, totIdx);
  pack_kernel<<<1, 640>>>(W1, tau_m, tau_n, mask, W2, b2);
  snn_kernel<<<Bb, 32>>>(x);
  loss_kernel<<<(Bb*Tt + 255)/256, 256>>>(target, out, corrIdx);
}

// round 9
// speedup vs baseline: 1.1485x; 1.1485x over previous
#include <cuda_runtime.h>
#include <cstdint>

typedef unsigned long long ull;

#define Bb 2048
#define Tt 1000
#define Ii 40
#define Hh 16
#define TS 20
#define NCH (Tt/TS)
#define PADF 8
#define BSTR (TS*Ii + PADF)     /* 808 floats per batch-sub slot (16B aligned) */
#define BUFF (2*BSTR)           /* per-buffer floats (2 batch elems) */

// -------- device-global scratch (no allocation allowed) --------
__device__ float4 g_wpack[Hh*20];     // pre-scaled: branch0 pair *(oma*omb0), branch1 pair *(oma*omb1)
__device__ float  g_alpha[Hh];
__device__ float2 g_beta[Hh];
__device__ float2 g_w2[Hh];           // (W2[0][h], W2[1][h])
__device__ float2 g_b2c;
__device__ uint32_t g_masks[(Bb/2)*Tt];   // per-warp 32-bit spike masks (low16 = b0, high16 = b0+1)

// -------- packed f32x2 helpers --------
__device__ __forceinline__ ull pk2(float a, float b){ ull r; asm("mov.b64 %0,{%1,%2};":"=l"(r):"f"(a),"f"(b)); return r; }
__device__ __forceinline__ void upk2(ull v, float&a, float&b){ asm("mov.b64 {%0,%1},%2;":"=f"(a),"=f"(b):"l"(v)); }
__device__ __forceinline__ ull fma2(ull a, ull b, ull c){ ull d; asm("fma.rn.f32x2 %0,%1,%2,%3;":"=l"(d):"l"(a),"l"(b),"l"(c)); return d; }
__device__ __forceinline__ ull mul2(ull a, ull b){ ull d; asm("mul.rn.f32x2 %0,%1,%2;":"=l"(d):"l"(a),"l"(b)); return d; }
__device__ __forceinline__ ull add2(ull a, ull b){ ull d; asm("add.rn.f32x2 %0,%1,%2;":"=l"(d):"l"(a),"l"(b)); return d; }
// non-volatile: allow ptxas to schedule loads across steps
__device__ __forceinline__ void lds128(uint32_t a, ull&u, ull&v){ asm("ld.shared.v2.b64 {%0,%1},[%2];":"=l"(u),"=l"(v):"r"(a)); }
__device__ __forceinline__ void cpa16(uint32_t d, const void* s){ asm volatile("cp.async.cg.shared.global [%0],[%1],16;"::"r"(d),"l"(s)); }
__device__ __forceinline__ void cp_commit(){ asm volatile("cp.async.commit_group;"); }
__device__ __forceinline__ void stg32_lane0(int lane, uint32_t* p, uint32_t v){
  asm volatile("{ .reg .pred q; setp.eq.s32 q,%0,0; @q st.global.b32 [%1],%2; }"
               :: "r"(lane), "l"(p), "r"(v) : "memory");
}

// ---------------- init: scalar outputs ----------------
__global__ void init_kernel(float* __restrict__ out, long long corrIdx, long long totIdx){
  if (threadIdx.x == 0){
    out[0] = 0.0f;
    out[corrIdx] = 0.0f;
    int cnt = 0;
    for (int t=0;t<Tt;t++) cnt += ((t>10) && (((t-10)%15)>5)) ? 1 : 0;
    out[totIdx] = (float)cnt * (float)Bb;   // flags.sum() * B
  }
}

// ---------------- pack: pre-scale weights (parallel) ----------------
__global__ void pack_kernel(const float* __restrict__ W1, const float* __restrict__ tau_m,
                            const float* __restrict__ tau_n, const float* __restrict__ mask,
                            const float* __restrict__ W2, const float* __restrict__ b2){
  int tid = threadIdx.x;                    // 320 threads: (h, k) pairs
  if (tid < Hh*20){
    int h = tid / 20, k = tid % 20;
    float a = 1.0f/(1.0f + expf(-tau_m[h]));
    float oma = 1.0f - a;
    float be0 = 1.0f/(1.0f+expf(-tau_n[h*2+0]));
    float be1 = 1.0f/(1.0f+expf(-tau_n[h*2+1]));
    float s0 = oma*(1.0f-be0);
    float s1 = oma*(1.0f-be1);
    int r0 = (2*h)*Ii, r1 = (2*h+1)*Ii;
    float4 w;
    w.x = W1[r0+2*k]  *mask[r0+2*k]  *s0;
    w.y = W1[r0+2*k+1]*mask[r0+2*k+1]*s0;
    w.z = W1[r1+2*k]  *mask[r1+2*k]  *s1;
    w.w = W1[r1+2*k+1]*mask[r1+2*k+1]*s1;
    g_wpack[h*20+k] = w;
    if (k == 0){
      g_alpha[h] = a;
      g_beta[h]  = make_float2(be0, be1);
      g_w2[h]    = make_float2(W2[h], W2[Hh+h]);
    }
  }
  if (tid == 0) g_b2c = make_float2(b2[0], b2[1]);
}

// ---------------- main: sequential SNN recurrence, warp = 2 batch x 16 neurons ----------------
// (Byte-identical hot path to the best-measured Round-3 kernel.)
__global__ void __launch_bounds__(32) snn_kernel(const float* __restrict__ x){
  __shared__ __align__(16) float sx[2*BUFF];
  const int lane = threadIdx.x;
  const int bsub = lane >> 4;
  const int h    = lane & 15;
  const int b0   = blockIdx.x * 2;

  ull wa[20], wb[20];
  #pragma unroll
  for (int k=0;k<20;k++){ float4 w = g_wpack[h*20+k]; wa[k]=pk2(w.x,w.y); wb[k]=pk2(w.z,w.w); }
  const float alpha = g_alpha[h];
  const float2 bt  = g_beta[h];

  float d0=0.f, d1=0.f, mem=0.f;
  float asel = 0.f;                 // alpha if previous spike else 0 (computed off-path)
  uint32_t sbase = (uint32_t)__cvta_generic_to_shared(sx);

  uint32_t* mrow = g_masks + (size_t)blockIdx.x * Tt;

  const float4* xg0 = (const float4*)x + (size_t)b0     * Tt * 10;   // 40 f32 = 10 float4/step
  const float4* xg1 = (const float4*)x + (size_t)(b0+1) * Tt * 10;

  // stage chunk 0
  for (int j=lane;j<400;j+=32){
    int bs = (j>=200); int pos = j - bs*200;
    cpa16(sbase + (uint32_t)(bs*202+pos)*16u, (bs? xg1:xg0) + pos);
  }
  cp_commit();

  int buf = 0;
  for (int c=0;c<NCH;c++){
    if (c+1 < NCH){
      uint32_t sb = sbase + (uint32_t)((buf^1)*BUFF)*4u;
      const float4* p0 = xg0 + (size_t)(c+1)*TS*10;
      const float4* p1 = xg1 + (size_t)(c+1)*TS*10;
      for (int j=lane;j<400;j+=32){
        int bs = (j>=200); int pos = j - bs*200;
        cpa16(sb + (uint32_t)(bs*202+pos)*16u, (bs? p1:p0) + pos);
      }
      cp_commit();
      asm volatile("cp.async.wait_group 1;" ::: "memory");
    } else {
      asm volatile("cp.async.wait_group 0;" ::: "memory");
    }
    __syncwarp();

    uint32_t xaddr = sbase + (uint32_t)(buf*BUFF + bsub*BSTR)*4u;

    #pragma unroll 4
    for (int tt=0; tt<TS; tt++){
      // dense masked dot, both branches: 10 LDS.128 -> 20 ull x-pairs, consumed immediately
      ull p0a, p0b;
      lds128(xaddr, p0a, p0b);
      ull a0 = mul2(wa[0], p0a), a1 = mul2(wa[1], p0b);
      ull q0 = mul2(wb[0], p0a), q1 = mul2(wb[1], p0b);
      #pragma unroll
      for (int j=1;j<10;j++){
        ull xa, xb;
        lds128(xaddr + 16u*j, xa, xb);
        a0 = fma2(wa[2*j],   xa, a0);
        a1 = fma2(wa[2*j+1], xb, a1);
        q0 = fma2(wb[2*j],   xa, q0);
        q1 = fma2(wb[2*j+1], xb, q1);
      }
      float f0,f1;
      ull s0 = add2(a0,a1); upk2(s0,f0,f1); float c0 = f0+f1;   // already scaled by oma*omb0
      ull s1 = add2(q0,q1); upk2(s1,f0,f1); float c1 = f0+f1;

      // recurrence (folded scales): d' = beta*d' + c; mem = alpha*mem + l - asel_prev
      d0 = fmaf(bt.x, d0, c0);
      d1 = fmaf(bt.y, d1, c1);
      float l = d0 + d1;
      mem = fmaf(alpha, mem, l) - asel;
      bool sp = mem > 1.0f;
      asel = sp ? alpha : 0.0f;                      // for next step, off critical path
      uint32_t m = __ballot_sync(0xffffffffu, sp);
      stg32_lane0(lane, mrow + tt, m);

      xaddr += Ii*4;
    }
    mrow += TS;
    __syncwarp();
    buf ^= 1;
  }
}

// ---------------- logits + fast closed-form loss + accuracy ----------------
// thread = one (b,t) point; mask word shared by batch pair (low/high 16 bits).
__global__ void loss_kernel(const int* __restrict__ target, float* __restrict__ out,
                            long long corrIdx){
  // LUTs: logits contribution of each 8-neuron spike sub-mask
  __shared__ float2 lut0[256], lut1[256];
  for (int m = threadIdx.x; m < 256; m += blockDim.x){
    float2 a = make_float2(0.f,0.f), b = make_float2(0.f,0.f);
    #pragma unroll
    for (int j=0;j<8;j++){
      if ((m>>j)&1){
        float2 w = g_w2[j];   a.x += w.x; a.y += w.y;
        float2 v = g_w2[8+j]; b.x += v.x; b.y += v.y;
      }
    }
    lut0[m]=a; lut1[m]=b;
  }
  __syncthreads();

  int idx = blockIdx.x * blockDim.x + threadIdx.x;
  float lossv = 0.f, corr = 0.f;
  if (idx < Bb*Tt){
    int b = idx / Tt;
    int t = idx - b*Tt;
    uint32_t w32 = g_masks[(size_t)(b>>1)*Tt + t];
    uint32_t m16 = (w32 >> ((b&1)<<4)) & 0xFFFFu;
    float2 lo = lut0[m16 & 0xFF];
    float2 hi = lut1[(m16 >> 8) & 0xFF];
    float2 b2v = g_b2c;
    float z0 = lo.x + hi.x + b2v.x;
    float z1 = lo.y + hi.y + b2v.y;
    out[1 + 2*(size_t)idx]     = z0;
    out[1 + 2*(size_t)idx + 1] = z1;
    if ((t>10) && (((t-10)%15)>5)){
      int tgt = target[idx];
      // closed-form double-softmax CE for 2 classes:
      // q = p1-p0 = (e^s-1)/(e^s+1), s = z1-z0
      // loss = ln2 ± q/2 + q^2/8 - q^4/192 + q^6/2880   (|q|<=1, err<3e-5)
      float s  = z1 - z0;
      float e  = __expf(s);
      float r  = __fdividef(1.0f, 1.0f + e);
      float q  = (e - 1.0f) * r;
      float q2 = q*q;
      float even = 0.6931471805599453f
                 + q2*(0.125f + q2*(-5.208333333e-3f + q2*3.472222222e-4f));
      float lossp = even + ((tgt==0) ? 0.5f : -0.5f) * q;
      lossv = lossp * (1.0f/(float)Bb);
      corr  = ((((s>0.0f)?1:0)==tgt)) ? 1.0f : 0.0f;
    }
  }
  #pragma unroll
  for (int off=16; off; off>>=1){
    lossv += __shfl_xor_sync(0xffffffffu, lossv, off);
    corr  += __shfl_xor_sync(0xffffffffu, corr,  off);
  }
  __shared__ float sl[32], sc[32];
  int wq = threadIdx.x>>5, ln = threadIdx.x&31;
  if (ln==0){ sl[wq]=lossv; sc[wq]=corr; }
  __syncthreads();
  if (wq==0){
    int nw = blockDim.x>>5;
    lossv = (ln<nw)? sl[ln]:0.f;
    corr  = (ln<nw)? sc[ln]:0.f;
    #pragma unroll
    for (int off=4; off; off>>=1){
      lossv += __shfl_xor_sync(0xffffffffu,lossv,off);
      corr  += __shfl_xor_sync(0xffffffffu,corr, off);
    }
    if (ln==0){ atomicAdd(out, lossv); atomicAdd(out+corrIdx, corr); }
  }
}

extern "C" void kernel_launch(void* const* d_in, const int* in_sizes, int n_in,
                              void* d_out, int out_size){
  const float* x      = (const float*)d_in[0];
  const int*   target = (const int*)  d_in[1];
  const float* W1     = (const float*)d_in[2];
  const float* tau_m  = (const float*)d_in[3];
  const float* tau_n  = (const float*)d_in[4];
  const float* mask   = (const float*)d_in[5];
  const float* W2     = (const float*)d_in[6];
  const float* b2     = (const float*)d_in[7];
  float* out = (float*)d_out;
  long long corrIdx = (long long)out_size - 2;   // layout: [loss, logits(B*T*2), correct, total]
  long long totIdx  = (long long)out_size - 1;

  init_kernel<<<1, 32>>>(out, corrIdx, totIdx);
  pack_kernel<<<1, 320>>>(W1, tau_m, tau_n, mask, W2, b2);
  snn_kernel<<<Bb/2, 32>>>(x);
  loss_kernel<<<(Bb*Tt + 255)/256, 256>>>(target, out, corrIdx);
}

// round 10
// speedup vs baseline: 1.2703x; 1.1060x over previous
#include <cuda_runtime.h>
#include <cstdint>

typedef unsigned long long ull;

#define Bb 2048
#define Tt 1000
#define Ii 40
#define Hh 16
#define TS 20
#define NCH (Tt/TS)
#define PADF 8
#define BSTR (TS*Ii + PADF)     /* 808 floats per batch-sub slot (16B aligned) */
#define BUFF (2*BSTR)           /* per-buffer floats (2 batch elems) */
#define CHBYTES (TS*Ii*4)       /* 3200B per batch per chunk */

// -------- device-global scratch (no allocation allowed) --------
__device__ float4 g_wpack[Hh*20];     // pre-scaled: branch0 pair *(oma*omb0), branch1 pair *(oma*omb1)
__device__ float  g_alpha[Hh];
__device__ float2 g_beta[Hh];
__device__ float2 g_w2[Hh];           // (W2[0][h], W2[1][h])
__device__ float2 g_b2c;
__device__ uint32_t g_masks[(Bb/2)*Tt];   // per-warp 32-bit spike masks (low16 = b0, high16 = b0+1)

// -------- packed f32x2 helpers --------
__device__ __forceinline__ ull pk2(float a, float b){ ull r; asm("mov.b64 %0,{%1,%2};":"=l"(r):"f"(a),"f"(b)); return r; }
__device__ __forceinline__ void upk2(ull v, float&a, float&b){ asm("mov.b64 {%0,%1},%2;":"=f"(a),"=f"(b):"l"(v)); }
__device__ __forceinline__ ull fma2(ull a, ull b, ull c){ ull d; asm("fma.rn.f32x2 %0,%1,%2,%3;":"=l"(d):"l"(a),"l"(b),"l"(c)); return d; }
__device__ __forceinline__ ull mul2(ull a, ull b){ ull d; asm("mul.rn.f32x2 %0,%1,%2;":"=l"(d):"l"(a),"l"(b)); return d; }
__device__ __forceinline__ ull add2(ull a, ull b){ ull d; asm("add.rn.f32x2 %0,%1,%2;":"=l"(d):"l"(a),"l"(b)); return d; }
// non-volatile: allow ptxas to schedule loads across steps
__device__ __forceinline__ void lds128(uint32_t a, ull&u, ull&v){ asm("ld.shared.v2.b64 {%0,%1},[%2];":"=l"(u),"=l"(v):"r"(a)); }
__device__ __forceinline__ void stg32_lane0(int lane, uint32_t* p, uint32_t v){
  asm volatile("{ .reg .pred q; setp.eq.s32 q,%0,0; @q st.global.b32 [%1],%2; }"
               :: "r"(lane), "l"(p), "r"(v) : "memory");
}
// -------- TMA bulk copy + mbarrier --------
__device__ __forceinline__ void bulkcp(uint32_t dst, const void* src, uint32_t bytes, uint32_t bar){
  asm volatile("cp.async.bulk.shared::cta.global.mbarrier::complete_tx::bytes [%0],[%1],%2,[%3];"
               :: "r"(dst), "l"(src), "r"(bytes), "r"(bar) : "memory");
}
__device__ __forceinline__ void mbar_init(uint32_t bar, uint32_t cnt){
  asm volatile("mbarrier.init.shared.b64 [%0],%1;" :: "r"(bar), "r"(cnt) : "memory");
}
__device__ __forceinline__ void mbar_expect_tx(uint32_t bar, uint32_t bytes){
  asm volatile("mbarrier.arrive.expect_tx.shared.b64 _,[%0],%1;" :: "r"(bar), "r"(bytes) : "memory");
}
__device__ __forceinline__ void mbar_wait(uint32_t bar, uint32_t parity){
  uint32_t done;
  asm volatile("{\n\t.reg .pred p;\n\t"
               "mbarrier.try_wait.parity.acquire.cta.shared::cta.b64 p,[%1],%2;\n\t"
               "selp.b32 %0,1,0,p;\n\t}"
               : "=r"(done) : "r"(bar), "r"(parity) : "memory");
  if (!done){
    asm volatile("{\n\t.reg .pred P1;\n\t"
                 "WL_%=:\n\t"
                 "mbarrier.try_wait.parity.acquire.cta.shared::cta.b64 P1,[%0],%1,0x989680;\n\t"
                 "@P1 bra.uni WD_%=;\n\t"
                 "bra.uni WL_%=;\n\t"
                 "WD_%=:\n\t}"
                 :: "r"(bar), "r"(parity) : "memory");
  }
}

// ---------------- init: scalar outputs ----------------
__global__ void init_kernel(float* __restrict__ out, long long corrIdx, long long totIdx){
  if (threadIdx.x == 0){
    out[0] = 0.0f;
    out[corrIdx] = 0.0f;
    int cnt = 0;
    for (int t=0;t<Tt;t++) cnt += ((t>10) && (((t-10)%15)>5)) ? 1 : 0;
    out[totIdx] = (float)cnt * (float)Bb;   // flags.sum() * B
  }
}

// ---------------- pack: pre-scale weights (parallel) ----------------
__global__ void pack_kernel(const float* __restrict__ W1, const float* __restrict__ tau_m,
                            const float* __restrict__ tau_n, const float* __restrict__ mask,
                            const float* __restrict__ W2, const float* __restrict__ b2){
  int tid = threadIdx.x;                    // 320 threads: (h, k) pairs
  if (tid < Hh*20){
    int h = tid / 20, k = tid % 20;
    float a = 1.0f/(1.0f + expf(-tau_m[h]));
    float oma = 1.0f - a;
    float be0 = 1.0f/(1.0f+expf(-tau_n[h*2+0]));
    float be1 = 1.0f/(1.0f+expf(-tau_n[h*2+1]));
    float s0 = oma*(1.0f-be0);
    float s1 = oma*(1.0f-be1);
    int r0 = (2*h)*Ii, r1 = (2*h+1)*Ii;
    float4 w;
    w.x = W1[r0+2*k]  *mask[r0+2*k]  *s0;
    w.y = W1[r0+2*k+1]*mask[r0+2*k+1]*s0;
    w.z = W1[r1+2*k]  *mask[r1+2*k]  *s1;
    w.w = W1[r1+2*k+1]*mask[r1+2*k+1]*s1;
    g_wpack[h*20+k] = w;
    if (k == 0){
      g_alpha[h] = a;
      g_beta[h]  = make_float2(be0, be1);
      g_w2[h]    = make_float2(W2[h], W2[Hh+h]);
    }
  }
  if (tid == 0) g_b2c = make_float2(b2[0], b2[1]);
}

// ---------------- main: sequential SNN recurrence, warp = 2 batch x 16 neurons ----------------
// Identical hot path to the best-measured kernel; ONLY the x staging changed:
// cp.async (400 LDGSTS/chunk, rt=8cyc each) -> cp.async.bulk (2 instrs/chunk + mbarrier).
__global__ void __launch_bounds__(32) snn_kernel(const float* __restrict__ x){
  __shared__ __align__(16) float sx[2*BUFF];
  __shared__ __align__(8) ull smbar[2];
  const int lane = threadIdx.x;
  const int bsub = lane >> 4;
  const int h    = lane & 15;
  const int b0   = blockIdx.x * 2;

  ull wa[20], wb[20];
  #pragma unroll
  for (int k=0;k<20;k++){ float4 w = g_wpack[h*20+k]; wa[k]=pk2(w.x,w.y); wb[k]=pk2(w.z,w.w); }
  const float alpha = g_alpha[h];
  const float2 bt  = g_beta[h];

  float d0=0.f, d1=0.f, mem=0.f;
  float asel = 0.f;                 // alpha if previous spike else 0 (computed off-path)
  uint32_t sbase = (uint32_t)__cvta_generic_to_shared(sx);
  uint32_t barb  = (uint32_t)__cvta_generic_to_shared(smbar);

  uint32_t* mrow = g_masks + (size_t)blockIdx.x * Tt;

  const float* xg0 = x + (size_t)b0     * Tt * Ii;
  const float* xg1 = x + (size_t)(b0+1) * Tt * Ii;

  // init barriers + stage chunk 0 (single bulk copy per batch)
  if (lane == 0){
    mbar_init(barb,     1);
    mbar_init(barb + 8, 1);
  }
  __syncwarp();
  if (lane == 0){
    mbar_expect_tx(barb, 2*CHBYTES);
    bulkcp(sbase,            xg0, CHBYTES, barb);
    bulkcp(sbase + BSTR*4u,  xg1, CHBYTES, barb);
  }

  int buf = 0;
  uint32_t pha0 = 0, pha1 = 0;
  for (int c=0;c<NCH;c++){
    if (lane == 0 && c+1 < NCH){
      uint32_t nb   = barb + (uint32_t)((buf^1)*8);
      uint32_t sb   = sbase + (uint32_t)((buf^1)*BUFF)*4u;
      mbar_expect_tx(nb, 2*CHBYTES);
      bulkcp(sb,            xg0 + (size_t)(c+1)*TS*Ii, CHBYTES, nb);
      bulkcp(sb + BSTR*4u,  xg1 + (size_t)(c+1)*TS*Ii, CHBYTES, nb);
    }
    // wait for current buffer
    if (buf == 0){ mbar_wait(barb,     pha0); pha0 ^= 1; }
    else         { mbar_wait(barb + 8, pha1); pha1 ^= 1; }

    uint32_t xaddr = sbase + (uint32_t)(buf*BUFF + bsub*BSTR)*4u;

    #pragma unroll 4
    for (int tt=0; tt<TS; tt++){
      // dense masked dot, both branches: 10 LDS.128 -> 20 ull x-pairs, consumed immediately
      ull p0a, p0b;
      lds128(xaddr, p0a, p0b);
      ull a0 = mul2(wa[0], p0a), a1 = mul2(wa[1], p0b);
      ull q0 = mul2(wb[0], p0a), q1 = mul2(wb[1], p0b);
      #pragma unroll
      for (int j=1;j<10;j++){
        ull xa, xb;
        lds128(xaddr + 16u*j, xa, xb);
        a0 = fma2(wa[2*j],   xa, a0);
        a1 = fma2(wa[2*j+1], xb, a1);
        q0 = fma2(wb[2*j],   xa, q0);
        q1 = fma2(wb[2*j+1], xb, q1);
      }
      float f0,f1;
      ull s0 = add2(a0,a1); upk2(s0,f0,f1); float c0 = f0+f1;   // already scaled by oma*omb0
      ull s1 = add2(q0,q1); upk2(s1,f0,f1); float c1 = f0+f1;

      // recurrence (folded scales): d' = beta*d' + c; mem = alpha*mem + l - asel_prev
      d0 = fmaf(bt.x, d0, c0);
      d1 = fmaf(bt.y, d1, c1);
      float l = d0 + d1;
      mem = fmaf(alpha, mem, l) - asel;
      bool sp = mem > 1.0f;
      asel = sp ? alpha : 0.0f;                      // for next step, off critical path
      uint32_t m = __ballot_sync(0xffffffffu, sp);
      stg32_lane0(lane, mrow + tt, m);

      xaddr += Ii*4;
    }
    mrow += TS;
    buf ^= 1;
  }
}

// ---------------- logits + fast closed-form loss + accuracy ----------------
// thread = one (b,t) point; mask word shared by batch pair (low/high 16 bits).
__global__ void loss_kernel(const int* __restrict__ target, float* __restrict__ out,
                            long long corrIdx){
  // LUTs: logits contribution of each 8-neuron spike sub-mask
  __shared__ float2 lut0[256], lut1[256];
  for (int m = threadIdx.x; m < 256; m += blockDim.x){
    float2 a = make_float2(0.f,0.f), b = make_float2(0.f,0.f);
    #pragma unroll
    for (int j=0;j<8;j++){
      if ((m>>j)&1){
        float2 w = g_w2[j];   a.x += w.x; a.y += w.y;
        float2 v = g_w2[8+j]; b.x += v.x; b.y += v.y;
      }
    }
    lut0[m]=a; lut1[m]=b;
  }
  __syncthreads();

  int idx = blockIdx.x * blockDim.x + threadIdx.x;
  float lossv = 0.f, corr = 0.f;
  if (idx < Bb*Tt){
    int b = idx / Tt;
    int t = idx - b*Tt;
    uint32_t w32 = g_masks[(size_t)(b>>1)*Tt + t];
    uint32_t m16 = (w32 >> ((b&1)<<4)) & 0xFFFFu;
    float2 lo = lut0[m16 & 0xFF];
    float2 hi = lut1[(m16 >> 8) & 0xFF];
    float2 b2v = g_b2c;
    float z0 = lo.x + hi.x + b2v.x;
    float z1 = lo.y + hi.y + b2v.y;
    out[1 + 2*(size_t)idx]     = z0;
    out[1 + 2*(size_t)idx + 1] = z1;
    if ((t>10) && (((t-10)%15)>5)){
      int tgt = target[idx];
      // closed-form double-softmax CE for 2 classes:
      // q = p1-p0 = (e^s-1)/(e^s+1), s = z1-z0
      // loss = ln2 ± q/2 + q^2/8 - q^4/192 + q^6/2880   (|q|<=1, err<3e-5)
      float s  = z1 - z0;
      float e  = __expf(s);
      float r  = __fdividef(1.0f, 1.0f + e);
      float q  = (e - 1.0f) * r;
      float q2 = q*q;
      float even = 0.6931471805599453f
                 + q2*(0.125f + q2*(-5.208333333e-3f + q2*3.472222222e-4f));
      float lossp = even + ((tgt==0) ? 0.5f : -0.5f) * q;
      lossv = lossp * (1.0f/(float)Bb);
      corr  = ((((s>0.0f)?1:0)==tgt)) ? 1.0f : 0.0f;
    }
  }
  #pragma unroll
  for (int off=16; off; off>>=1){
    lossv += __shfl_xor_sync(0xffffffffu, lossv, off);
    corr  += __shfl_xor_sync(0xffffffffu, corr,  off);
  }
  __shared__ float sl[32], sc[32];
  int wq = threadIdx.x>>5, ln = threadIdx.x&31;
  if (ln==0){ sl[wq]=lossv; sc[wq]=corr; }
  __syncthreads();
  if (wq==0){
    int nw = blockDim.x>>5;
    lossv = (ln<nw)? sl[ln]:0.f;
    corr  = (ln<nw)? sc[ln]:0.f;
    #pragma unroll
    for (int off=4; off; off>>=1){
      lossv += __shfl_xor_sync(0xffffffffu,lossv,off);
      corr  += __shfl_xor_sync(0xffffffffu,corr, off);
    }
    if (ln==0){ atomicAdd(out, lossv); atomicAdd(out+corrIdx, corr); }
  }
}

extern "C" void kernel_launch(void* const* d_in, const int* in_sizes, int n_in,
                              void* d_out, int out_size){
  const float* x      = (const float*)d_in[0];
  const int*   target = (const int*)  d_in[1];
  const float* W1     = (const float*)d_in[2];
  const float* tau_m  = (const float*)d_in[3];
  const float* tau_n  = (const float*)d_in[4];
  const float* mask   = (const float*)d_in[5];
  const float* W2     = (const float*)d_in[6];
  const float* b2     = (const float*)d_in[7];
  float* out = (float*)d_out;
  long long corrIdx = (long long)out_size - 2;   // layout: [loss, logits(B*T*2), correct, total]
  long long totIdx  = (long long)out_size - 1;

  init_kernel<<<1, 32>>>(out, corrIdx, totIdx);
  pack_kernel<<<1, 320>>>(W1, tau_m, tau_n, mask, W2, b2);
  snn_kernel<<<Bb/2, 32>>>(x);
  loss_kernel<<<(Bb*Tt + 255)/256, 256>>>(target, out, corrIdx);
}